// round 9
// baseline (speedup 1.0000x reference)
#include <cuda_runtime.h>
#include <math.h>

// ---------------------------------------------------------------------------
// ann2_snn1 — bit-exact emulation of the JAX/XLA fp32 reference, optimized.
//   h     = relu(inputs @ w1.T + b1)        k-sequential FFMA chains
//   drive = sigmoid(h @ w2.T + b2)          sigmoid = 0.5+0.5*tanh(0.5x), XLA tanh
//   scan: psp = a1*p1 + a2*p2 + drive       separate fp32 roundings
//         cur = psp @ w3.T + b3             k-sequential FFMA chains
//         v   = sigma*v*(1-s) + cur ; s = (v>=1)
// ---------------------------------------------------------------------------

#define BM 64
#define BN 64
#define BK 32

#define BATCH 1024
#define H1 500
#define H2 500
#define NIN 784
#define NOUT 10
#define TSTEPS 100

#define HT 512              // head threads
#define HROW 132            // hist row stride in floats (33 float4, odd)

// scratch (no cudaMalloc allowed)
__device__ float g_h[BATCH * H1];
__device__ float g_drive[BATCH * H2];

// XLA F32 tanh rational approximation (matches reference bit-for-bit).
__device__ __forceinline__ float xla_tanh_f32(float x)
{
    const float kMax = 7.90531110763549805f;
    float ax = fabsf(x);
    float xc = fminf(fmaxf(x, -kMax), kMax);
    float x2 = __fmul_rn(xc, xc);

    float np = -2.76076847742355e-16f;
    np = fmaf(np, x2, 2.00018790482477e-13f);
    np = fmaf(np, x2, -8.60467152213735e-11f);
    np = fmaf(np, x2, 5.12229709037114e-08f);
    np = fmaf(np, x2, 1.48572235717979e-05f);
    np = fmaf(np, x2, 6.37261928875436e-04f);
    np = fmaf(np, x2, 4.89352455891786e-03f);
    float num = __fmul_rn(xc, np);

    float dp = 1.19825839466702e-06f;
    dp = fmaf(dp, x2, 1.18534705686654e-04f);
    dp = fmaf(dp, x2, 2.26843463243900e-03f);
    dp = fmaf(dp, x2, 4.89352518554385e-03f);

    float r = __fdiv_rn(num, dp);
    return (ax < 0.0004f) ? x : r;
}

__device__ __forceinline__ float4 ld4_guard(const float* row, int k, int K)
{
    if (k + 4 <= K)
        return *reinterpret_cast<const float4*>(row + k);
    float4 v;
    v.x = (k + 0 < K) ? row[k + 0] : 0.f;
    v.y = (k + 1 < K) ? row[k + 1] : 0.f;
    v.z = (k + 2 < K) ? row[k + 2] : 0.f;
    v.w = (k + 3 < K) ? row[k + 3] : 0.f;
    return v;
}

// C[M,N] = act(A[M,K] @ B[N,K]^T + bias[N]); ACT 0=relu, 1=xla-sigmoid.
// Double-buffered smem, register prefetch, ONE sync per 32-wide K-tile.
// Per-element accumulation strictly k-ascending single-acc fmaf; zero-padded
// tail fmaf(0,*,acc)==acc exactly, so bit-exactness is preserved.
template <int ACT>
__global__ __launch_bounds__(256)
void gemm_bias_act(const float* __restrict__ A, const float* __restrict__ B,
                   const float* __restrict__ bias, float* __restrict__ C,
                   int M, int N, int K)
{
    __shared__ float As[2][BK][BM];
    __shared__ float Bs[2][BK][BN];

    const int tid = threadIdx.x;
    const int lr  = tid >> 2;           // 0..63 row within tile (loading)
    const int kq  = (tid & 3) << 2;     // 0,4,8,12 ; second load at +16
    const int ty  = tid >> 4;           // 0..15
    const int tx  = tid & 15;           // 0..15

    const int gm = blockIdx.y * BM + lr;   // M=1024, always valid
    const int gn = blockIdx.x * BN + lr;   // may exceed N

    const float* Arow = A + (size_t)gm * K;
    const float* Brow = B + (size_t)gn * K;
    const bool bn_ok  = (gn < N);

    const int nIter = (K + BK - 1) / BK;

    // prologue: tile 0 -> buf 0
    {
        float4 a0 = ld4_guard(Arow, kq, K);
        float4 a1 = ld4_guard(Arow, kq + 16, K);
        float4 b0 = bn_ok ? ld4_guard(Brow, kq, K)      : make_float4(0,0,0,0);
        float4 b1 = bn_ok ? ld4_guard(Brow, kq + 16, K) : make_float4(0,0,0,0);
        As[0][kq + 0][lr] = a0.x; As[0][kq + 1][lr] = a0.y;
        As[0][kq + 2][lr] = a0.z; As[0][kq + 3][lr] = a0.w;
        As[0][kq + 16][lr] = a1.x; As[0][kq + 17][lr] = a1.y;
        As[0][kq + 18][lr] = a1.z; As[0][kq + 19][lr] = a1.w;
        Bs[0][kq + 0][lr] = b0.x; Bs[0][kq + 1][lr] = b0.y;
        Bs[0][kq + 2][lr] = b0.z; Bs[0][kq + 3][lr] = b0.w;
        Bs[0][kq + 16][lr] = b1.x; Bs[0][kq + 17][lr] = b1.y;
        Bs[0][kq + 18][lr] = b1.z; Bs[0][kq + 19][lr] = b1.w;
    }
    __syncthreads();

    float acc[4][4] = {};
    int buf = 0;

    for (int it = 0; it < nIter; ++it) {
        float4 a0, a1, b0, b1;
        const bool more = (it + 1 < nIter);
        if (more) {
            const int ka = (it + 1) * BK + kq;
            a0 = ld4_guard(Arow, ka, K);
            a1 = ld4_guard(Arow, ka + 16, K);
            b0 = bn_ok ? ld4_guard(Brow, ka, K)      : make_float4(0,0,0,0);
            b1 = bn_ok ? ld4_guard(Brow, ka + 16, K) : make_float4(0,0,0,0);
        }

        #pragma unroll
        for (int kk = 0; kk < BK; kk++) {             // k ascending
            float4 a = *reinterpret_cast<const float4*>(&As[buf][kk][ty << 2]);
            float4 b = *reinterpret_cast<const float4*>(&Bs[buf][kk][tx << 2]);
            float ar[4] = {a.x, a.y, a.z, a.w};
            float br[4] = {b.x, b.y, b.z, b.w};
            #pragma unroll
            for (int i = 0; i < 4; i++)
                #pragma unroll
                for (int j = 0; j < 4; j++)
                    acc[i][j] = fmaf(ar[i], br[j], acc[i][j]);
        }

        if (more) {
            const int nb = buf ^ 1;
            As[nb][kq + 0][lr] = a0.x; As[nb][kq + 1][lr] = a0.y;
            As[nb][kq + 2][lr] = a0.z; As[nb][kq + 3][lr] = a0.w;
            As[nb][kq + 16][lr] = a1.x; As[nb][kq + 17][lr] = a1.y;
            As[nb][kq + 18][lr] = a1.z; As[nb][kq + 19][lr] = a1.w;
            Bs[nb][kq + 0][lr] = b0.x; Bs[nb][kq + 1][lr] = b0.y;
            Bs[nb][kq + 2][lr] = b0.z; Bs[nb][kq + 3][lr] = b0.w;
            Bs[nb][kq + 16][lr] = b1.x; Bs[nb][kq + 17][lr] = b1.y;
            Bs[nb][kq + 18][lr] = b1.z; Bs[nb][kq + 19][lr] = b1.w;
        }
        __syncthreads();
        buf ^= 1;
    }

    const int om = blockIdx.y * BM + (ty << 2);
    const int on = blockIdx.x * BN + (tx << 2);
    #pragma unroll
    for (int j = 0; j < 4; j++) {
        const int n = on + j;
        if (n >= N) continue;
        const float bb = bias[n];
        #pragma unroll
        for (int i = 0; i < 4; i++) {
            float z = __fadd_rn(acc[i][j], bb);
            float v;
            if (ACT == 0) {
                v = fmaxf(z, 0.f);
            } else {
                float th = xla_tanh_f32(__fmul_rn(0.5f, z));
                v = __fadd_rn(0.5f, __fmul_rn(0.5f, th));
            }
            C[(size_t)(om + i) * N + n] = v;
        }
    }
}

// Head: one block per batch row, 512 threads, K chunked {128,128,128,116}.
// Phase-2 thread map t=tid/5, og=tid%5 -> a warp touches only ~7 distinct hist
// rows (broadcast in 5-lane groups) + 10 weight rows: crossbar traffic halved
// vs t=tid%100 map, making phase 2 FFMA-bound. Accumulators live in registers
// across chunks -> each (t,o) chain is one k-ascending fmaf chain (bit-exact).
__global__ __launch_bounds__(HT, 2)
void snn_head(const float* __restrict__ drive, const float* __restrict__ w3,
              const float* __restrict__ b3, float* __restrict__ out,
              float a1, float a2, float sigma)
{
    extern __shared__ float sm[];
    float* hist = sm;                       // [TSTEPS][HROW]
    float* w3s  = sm + TSTEPS * HROW;       // [NOUT][H2] = 5000
    float* curs = w3s + NOUT * H2;          // [TSTEPS][NOUT] = 1000
    float* spk  = curs + TSTEPS * NOUT;     // [NOUT][TSTEPS] = 1000

    const int b   = blockIdx.x;
    const int tid = threadIdx.x;

    for (int i = tid; i < NOUT * H2; i += HT)
        w3s[i] = w3[i];

    const int t  = tid / 5;        // phase-2 time index   (tid < 500)
    const int og = tid % 5;        // phase-2 output pair  0..4
    float acc0 = 0.f, acc1 = 0.f;

    #pragma unroll
    for (int c = 0; c < 4; ++c) {
        const int k0   = c * 128;
        const int klen = (c < 3) ? 128 : 116;

        // Phase 1: per-k psp recurrence for this k-chunk (exact roundings)
        if (tid < klen) {
            const float d = drive[(size_t)b * H2 + k0 + tid];
            float p1 = 0.f, p2 = 0.f;
            #pragma unroll 4
            for (int tt = 0; tt < TSTEPS; ++tt) {
                float ps = __fadd_rn(
                    __fadd_rn(__fmul_rn(a1, p1), __fmul_rn(a2, p2)), d);
                hist[tt * HROW + tid] = ps;
                p2 = p1;
                p1 = ps;
            }
        }
        __syncthreads();

        // Phase 2: continue k-ascending fmaf chains for (t, 2og) and (t, 2og+1)
        if (tid < 500) {
            const float4* h4 = reinterpret_cast<const float4*>(hist) + t * (HROW / 4);
            const float4* wA = reinterpret_cast<const float4*>(w3s + (og * 2 + 0) * H2 + k0);
            const float4* wB = reinterpret_cast<const float4*>(w3s + (og * 2 + 1) * H2 + k0);
            const int nq = klen >> 2;
            #pragma unroll 8
            for (int j = 0; j < nq; ++j) {
                float4 h = h4[j];
                float4 a = wA[j];
                float4 w = wB[j];
                acc0 = fmaf(h.x, a.x, acc0);
                acc0 = fmaf(h.y, a.y, acc0);
                acc0 = fmaf(h.z, a.z, acc0);
                acc0 = fmaf(h.w, a.w, acc0);
                acc1 = fmaf(h.x, w.x, acc1);
                acc1 = fmaf(h.y, w.y, acc1);
                acc1 = fmaf(h.z, w.z, acc1);
                acc1 = fmaf(h.w, w.w, acc1);
            }
        }
        __syncthreads();   // hist reused next chunk
    }

    if (tid < 500) {
        curs[t * NOUT + og * 2 + 0] = __fadd_rn(acc0, b3[og * 2 + 0]);
        curs[t * NOUT + og * 2 + 1] = __fadd_rn(acc1, b3[og * 2 + 1]);
    }
    __syncthreads();

    // Phase 3: membrane scan, separate roundings, spikes to smem
    if (tid < NOUT) {
        float v = 0.f, s = 0.f;
        #pragma unroll 4
        for (int tt = 0; tt < TSTEPS; ++tt) {
            float m = __fmul_rn(__fmul_rn(sigma, v), __fsub_rn(1.0f, s));
            v = __fadd_rn(m, curs[tt * NOUT + tid]);
            s = (v >= 1.0f) ? 1.0f : 0.0f;
            spk[tid * TSTEPS + tt] = s;    // [o][t] matches out layout
        }
    }
    __syncthreads();

    // coalesced writeback: 1000 contiguous floats per block
    float4* o4 = reinterpret_cast<float4*>(out + (size_t)b * NOUT * TSTEPS);
    const float4* s4 = reinterpret_cast<const float4*>(spk);
    if (tid < NOUT * TSTEPS / 4)
        o4[tid] = s4[tid];
}

extern "C" void kernel_launch(void* const* d_in, const int* in_sizes, int n_in,
                              void* d_out, int out_size)
{
    const float* inputs = (const float*)d_in[0];  // [1024, 784]
    const float* w1     = (const float*)d_in[1];  // [500, 784]
    const float* b1     = (const float*)d_in[2];  // [500]
    const float* w2     = (const float*)d_in[3];  // [500, 500]
    const float* b2     = (const float*)d_in[4];  // [500]
    const float* w3     = (const float*)d_in[5];  // [10, 500]
    const float* b3     = (const float*)d_in[6];  // [10]
    float* out          = (float*)d_out;          // [1024, 10, 100]

    float *h = nullptr, *drive = nullptr;
    cudaGetSymbolAddress((void**)&h, g_h);
    cudaGetSymbolAddress((void**)&drive, g_drive);

    const double em = exp(-1.0 / 4.0);
    const double es = exp(-1.0 / 1.0);
    const float a1f = (float)(em + es);
    const float a2f = (float)(-em * es);
    const float sgf = (float)em;

    dim3 blk(256);
    dim3 g1((H1 + BN - 1) / BN, (BATCH + BM - 1) / BM);   // (8, 16)
    gemm_bias_act<0><<<g1, blk>>>(inputs, w1, b1, h, BATCH, H1, NIN);
    gemm_bias_act<1><<<g1, blk>>>(h, w2, b2, drive, BATCH, H2, H1);

    const int head_smem =
        (TSTEPS * HROW + NOUT * H2 + 2 * TSTEPS * NOUT) * sizeof(float);
    cudaFuncSetAttribute(snn_head, cudaFuncAttributeMaxDynamicSharedMemorySize,
                         head_smem);
    snn_head<<<BATCH, HT, head_smem>>>(drive, w3, b3, out, a1f, a2f, sgf);
}

// round 10
// speedup vs baseline: 1.6278x; 1.6278x over previous
#include <cuda_runtime.h>
#include <math.h>

// ---------------------------------------------------------------------------
// ann2_snn1 — bit-exact emulation of the JAX/XLA fp32 reference, optimized.
//   h     = relu(inputs @ w1.T + b1)        k-sequential FFMA chains
//   drive = sigmoid(h @ w2.T + b2)          sigmoid = 0.5+0.5*tanh(0.5x), XLA tanh
//   scan: psp = a1*p1 + a2*p2 + drive       separate fp32 roundings
//         cur = psp @ w3.T + b3             k-sequential FFMA chains
//         v   = sigma*v*(1-s) + cur ; s = (v>=1)
// ---------------------------------------------------------------------------

#define BM 64
#define BN 64
#define BK 32

#define BATCH 1024
#define H1 500
#define H2 500
#define NIN 784
#define NOUT 10
#define TSTEPS 100

#define HT 512              // head threads
#define HROW 132            // hist row stride in floats (33 float4: stride 1 mod 8
                            // bank-groups per quarter-warp -> conflict-free)

// scratch (no cudaMalloc allowed)
__device__ float g_h[BATCH * H1];
__device__ float g_drive[BATCH * H2];

// XLA F32 tanh rational approximation (matches reference bit-for-bit).
__device__ __forceinline__ float xla_tanh_f32(float x)
{
    const float kMax = 7.90531110763549805f;
    float ax = fabsf(x);
    float xc = fminf(fmaxf(x, -kMax), kMax);
    float x2 = __fmul_rn(xc, xc);

    float np = -2.76076847742355e-16f;
    np = fmaf(np, x2, 2.00018790482477e-13f);
    np = fmaf(np, x2, -8.60467152213735e-11f);
    np = fmaf(np, x2, 5.12229709037114e-08f);
    np = fmaf(np, x2, 1.48572235717979e-05f);
    np = fmaf(np, x2, 6.37261928875436e-04f);
    np = fmaf(np, x2, 4.89352455891786e-03f);
    float num = __fmul_rn(xc, np);

    float dp = 1.19825839466702e-06f;
    dp = fmaf(dp, x2, 1.18534705686654e-04f);
    dp = fmaf(dp, x2, 2.26843463243900e-03f);
    dp = fmaf(dp, x2, 4.89352518554385e-03f);

    float r = __fdiv_rn(num, dp);
    return (ax < 0.0004f) ? x : r;
}

__device__ __forceinline__ float4 ld4_guard(const float* row, int k, int K)
{
    if (k + 4 <= K)
        return *reinterpret_cast<const float4*>(row + k);
    float4 v;
    v.x = (k + 0 < K) ? row[k + 0] : 0.f;
    v.y = (k + 1 < K) ? row[k + 1] : 0.f;
    v.z = (k + 2 < K) ? row[k + 2] : 0.f;
    v.w = (k + 3 < K) ? row[k + 3] : 0.f;
    return v;
}

// C[M,N] = act(A[M,K] @ B[N,K]^T + bias[N]); ACT 0=relu, 1=xla-sigmoid.
// Double-buffered smem, register prefetch, ONE sync per 32-wide K-tile.
// Per-element accumulation strictly k-ascending single-acc fmaf; zero-padded
// tail fmaf(0,*,acc)==acc exactly, so bit-exactness is preserved.
template <int ACT>
__global__ __launch_bounds__(256)
void gemm_bias_act(const float* __restrict__ A, const float* __restrict__ B,
                   const float* __restrict__ bias, float* __restrict__ C,
                   int M, int N, int K)
{
    __shared__ float As[2][BK][BM];
    __shared__ float Bs[2][BK][BN];

    const int tid = threadIdx.x;
    const int lr  = tid >> 2;           // 0..63 row within tile (loading)
    const int kq  = (tid & 3) << 2;     // 0,4,8,12 ; second load at +16
    const int ty  = tid >> 4;           // 0..15
    const int tx  = tid & 15;           // 0..15

    const int gm = blockIdx.y * BM + lr;   // M=1024, always valid
    const int gn = blockIdx.x * BN + lr;   // may exceed N

    const float* Arow = A + (size_t)gm * K;
    const float* Brow = B + (size_t)gn * K;
    const bool bn_ok  = (gn < N);

    const int nIter = (K + BK - 1) / BK;

    // prologue: tile 0 -> buf 0
    {
        float4 a0 = ld4_guard(Arow, kq, K);
        float4 a1 = ld4_guard(Arow, kq + 16, K);
        float4 b0 = bn_ok ? ld4_guard(Brow, kq, K)      : make_float4(0,0,0,0);
        float4 b1 = bn_ok ? ld4_guard(Brow, kq + 16, K) : make_float4(0,0,0,0);
        As[0][kq + 0][lr] = a0.x; As[0][kq + 1][lr] = a0.y;
        As[0][kq + 2][lr] = a0.z; As[0][kq + 3][lr] = a0.w;
        As[0][kq + 16][lr] = a1.x; As[0][kq + 17][lr] = a1.y;
        As[0][kq + 18][lr] = a1.z; As[0][kq + 19][lr] = a1.w;
        Bs[0][kq + 0][lr] = b0.x; Bs[0][kq + 1][lr] = b0.y;
        Bs[0][kq + 2][lr] = b0.z; Bs[0][kq + 3][lr] = b0.w;
        Bs[0][kq + 16][lr] = b1.x; Bs[0][kq + 17][lr] = b1.y;
        Bs[0][kq + 18][lr] = b1.z; Bs[0][kq + 19][lr] = b1.w;
    }
    __syncthreads();

    float acc[4][4] = {};
    int buf = 0;

    for (int it = 0; it < nIter; ++it) {
        float4 a0, a1, b0, b1;
        const bool more = (it + 1 < nIter);
        if (more) {
            const int ka = (it + 1) * BK + kq;
            a0 = ld4_guard(Arow, ka, K);
            a1 = ld4_guard(Arow, ka + 16, K);
            b0 = bn_ok ? ld4_guard(Brow, ka, K)      : make_float4(0,0,0,0);
            b1 = bn_ok ? ld4_guard(Brow, ka + 16, K) : make_float4(0,0,0,0);
        }

        #pragma unroll
        for (int kk = 0; kk < BK; kk++) {             // k ascending
            float4 a = *reinterpret_cast<const float4*>(&As[buf][kk][ty << 2]);
            float4 b = *reinterpret_cast<const float4*>(&Bs[buf][kk][tx << 2]);
            float ar[4] = {a.x, a.y, a.z, a.w};
            float br[4] = {b.x, b.y, b.z, b.w};
            #pragma unroll
            for (int i = 0; i < 4; i++)
                #pragma unroll
                for (int j = 0; j < 4; j++)
                    acc[i][j] = fmaf(ar[i], br[j], acc[i][j]);
        }

        if (more) {
            const int nb = buf ^ 1;
            As[nb][kq + 0][lr] = a0.x; As[nb][kq + 1][lr] = a0.y;
            As[nb][kq + 2][lr] = a0.z; As[nb][kq + 3][lr] = a0.w;
            As[nb][kq + 16][lr] = a1.x; As[nb][kq + 17][lr] = a1.y;
            As[nb][kq + 18][lr] = a1.z; As[nb][kq + 19][lr] = a1.w;
            Bs[nb][kq + 0][lr] = b0.x; Bs[nb][kq + 1][lr] = b0.y;
            Bs[nb][kq + 2][lr] = b0.z; Bs[nb][kq + 3][lr] = b0.w;
            Bs[nb][kq + 16][lr] = b1.x; Bs[nb][kq + 17][lr] = b1.y;
            Bs[nb][kq + 18][lr] = b1.z; Bs[nb][kq + 19][lr] = b1.w;
        }
        __syncthreads();
        buf ^= 1;
    }

    const int om = blockIdx.y * BM + (ty << 2);
    const int on = blockIdx.x * BN + (tx << 2);
    #pragma unroll
    for (int j = 0; j < 4; j++) {
        const int n = on + j;
        if (n >= N) continue;
        const float bb = bias[n];
        #pragma unroll
        for (int i = 0; i < 4; i++) {
            float z = __fadd_rn(acc[i][j], bb);
            float v;
            if (ACT == 0) {
                v = fmaxf(z, 0.f);
            } else {
                float th = xla_tanh_f32(__fmul_rn(0.5f, z));
                v = __fadd_rn(0.5f, __fmul_rn(0.5f, th));
            }
            C[(size_t)(om + i) * N + n] = v;
        }
    }
}

// Head: one block per batch row, 512 threads, K chunked {128,128,128,116}.
// Phase-2 map: t = tid%100 (per-lane, distinct conflict-free hist rows),
// oq = tid/100 -> thread owns 5 outputs. Weight reads stay warp-BROADCAST
// (uniform oq within almost every warp): per warp-j = 4 cyc hist + 5 cyc
// weights of LDS for 40 FFMA-issue-cycles -> FFMA-bound. Accumulators live in
// registers across chunks -> each (t,o) chain is one k-ascending fmaf chain.
__global__ __launch_bounds__(HT, 2)
void snn_head(const float* __restrict__ drive, const float* __restrict__ w3,
              const float* __restrict__ b3, float* __restrict__ out,
              float a1, float a2, float sigma)
{
    extern __shared__ float sm[];
    float* hist = sm;                       // [TSTEPS][HROW]
    float* w3s  = sm + TSTEPS * HROW;       // [NOUT][H2] = 5000
    float* curs = w3s + NOUT * H2;          // [TSTEPS][NOUT] = 1000
    float* spk  = curs + TSTEPS * NOUT;     // [NOUT][TSTEPS] = 1000

    const int b   = blockIdx.x;
    const int tid = threadIdx.x;

    for (int i = tid; i < NOUT * H2; i += HT)
        w3s[i] = w3[i];

    const int t  = tid % 100;      // phase-2 time index   (tid < 200)
    const int oq = tid / 100;      // phase-2 output group: 5 outputs each
    float acc[5] = {0.f, 0.f, 0.f, 0.f, 0.f};

    #pragma unroll
    for (int c = 0; c < 4; ++c) {
        const int k0   = c * 128;
        const int klen = (c < 3) ? 128 : 116;

        // Phase 1: per-k psp recurrence for this k-chunk (exact roundings)
        if (tid < klen) {
            const float d = drive[(size_t)b * H2 + k0 + tid];
            float p1 = 0.f, p2 = 0.f;
            #pragma unroll 4
            for (int tt = 0; tt < TSTEPS; ++tt) {
                float ps = __fadd_rn(
                    __fadd_rn(__fmul_rn(a1, p1), __fmul_rn(a2, p2)), d);
                hist[tt * HROW + tid] = ps;
                p2 = p1;
                p1 = ps;
            }
        }
        __syncthreads();

        // Phase 2: continue 5 k-ascending fmaf chains for outputs oq*5..oq*5+4
        if (tid < 200) {
            const float4* h4 = reinterpret_cast<const float4*>(hist) + t * (HROW / 4);
            const int nq = klen >> 2;
            #pragma unroll 4
            for (int j = 0; j < nq; ++j) {
                float4 h = h4[j];
                #pragma unroll
                for (int o = 0; o < 5; ++o) {
                    float4 w = *reinterpret_cast<const float4*>(
                        w3s + (oq * 5 + o) * H2 + k0 + (j << 2));
                    float a = acc[o];
                    a = fmaf(h.x, w.x, a);
                    a = fmaf(h.y, w.y, a);
                    a = fmaf(h.z, w.z, a);
                    a = fmaf(h.w, w.w, a);
                    acc[o] = a;
                }
            }
        }
        __syncthreads();   // hist reused next chunk
    }

    if (tid < 200) {
        #pragma unroll
        for (int o = 0; o < 5; ++o)
            curs[t * NOUT + oq * 5 + o] = __fadd_rn(acc[o], b3[oq * 5 + o]);
    }
    __syncthreads();

    // Phase 3: membrane scan, separate roundings, spikes to smem
    if (tid < NOUT) {
        float v = 0.f, s = 0.f;
        #pragma unroll 4
        for (int tt = 0; tt < TSTEPS; ++tt) {
            float m = __fmul_rn(__fmul_rn(sigma, v), __fsub_rn(1.0f, s));
            v = __fadd_rn(m, curs[tt * NOUT + tid]);
            s = (v >= 1.0f) ? 1.0f : 0.0f;
            spk[tid * TSTEPS + tt] = s;    // [o][t] matches out layout
        }
    }
    __syncthreads();

    // coalesced writeback: 1000 contiguous floats per block
    float4* o4 = reinterpret_cast<float4*>(out + (size_t)b * NOUT * TSTEPS);
    const float4* s4 = reinterpret_cast<const float4*>(spk);
    if (tid < NOUT * TSTEPS / 4)
        o4[tid] = s4[tid];
}

extern "C" void kernel_launch(void* const* d_in, const int* in_sizes, int n_in,
                              void* d_out, int out_size)
{
    const float* inputs = (const float*)d_in[0];  // [1024, 784]
    const float* w1     = (const float*)d_in[1];  // [500, 784]
    const float* b1     = (const float*)d_in[2];  // [500]
    const float* w2     = (const float*)d_in[3];  // [500, 500]
    const float* b2     = (const float*)d_in[4];  // [500]
    const float* w3     = (const float*)d_in[5];  // [10, 500]
    const float* b3     = (const float*)d_in[6];  // [10]
    float* out          = (float*)d_out;          // [1024, 10, 100]

    float *h = nullptr, *drive = nullptr;
    cudaGetSymbolAddress((void**)&h, g_h);
    cudaGetSymbolAddress((void**)&drive, g_drive);

    const double em = exp(-1.0 / 4.0);
    const double es = exp(-1.0 / 1.0);
    const float a1f = (float)(em + es);
    const float a2f = (float)(-em * es);
    const float sgf = (float)em;

    dim3 blk(256);
    dim3 g1((H1 + BN - 1) / BN, (BATCH + BM - 1) / BM);   // (8, 16)
    gemm_bias_act<0><<<g1, blk>>>(inputs, w1, b1, h, BATCH, H1, NIN);
    gemm_bias_act<1><<<g1, blk>>>(h, w2, b2, drive, BATCH, H2, H1);

    const int head_smem =
        (TSTEPS * HROW + NOUT * H2 + 2 * TSTEPS * NOUT) * sizeof(float);
    cudaFuncSetAttribute(snn_head, cudaFuncAttributeMaxDynamicSharedMemorySize,
                         head_smem);
    snn_head<<<BATCH, HT, head_smem>>>(drive, w3, b3, out, a1f, a2f, sgf);
}